// round 16
// baseline (speedup 1.0000x reference)
#include <cuda_runtime.h>
#include <cuda_fp16.h>
#include <math.h>

#define NN   10000
#define EE   320000
#define DIM  176
#define ATT  16
#define SHH  16
#define THH  4
#define NHH  20
#define VD   11
#define NSPH 16
#define RDIMC 16
#define QKVW 816   // 320 + 320 + 176 (GEMM column space)

typedef unsigned long long u64;
typedef long long ll;

// ---------------- scratch ----------------
__device__ float  g_xi [NN * DIM];
__device__ __half g_qkh[NN * 640];   // per node: qT[320 half] | kT[320 half], head-transposed
__device__ float  g_v  [NN * DIM];   // per node: v[176] fp32
__device__ float  g_mi [NN * DIM];
__device__ float  g_Vi [NN * THH * NSPH];
__device__ float  g_Y  [EE * NSPH];
__device__ float  g_G  [NN * DIM];
__device__ float  g_w  [(ll)EE * 16];   // per-edge MLP output (switch-scaled)

// ---------------- helpers ----------------
__device__ __forceinline__ u64 pack2(float x, float y) {
    u64 r; asm("mov.b64 %0,{%1,%2};" : "=l"(r) : "f"(x), "f"(y)); return r;
}
__device__ __forceinline__ void fma2(u64& d, u64 a, u64 b) {
    asm("fma.rn.f32x2 %0, %1, %2, %3;" : "=l"(d) : "l"(a), "l"(b), "l"(d));
}
__device__ __forceinline__ float2 unpack2(u64 v) {
    float2 f; asm("mov.b64 {%0,%1},%2;" : "=f"(f.x), "=f"(f.y) : "l"(v)); return f;
}

__device__ __forceinline__ float block_sum_192(float v, float* red) {
    #pragma unroll
    for (int o = 16; o; o >>= 1) v += __shfl_xor_sync(0xffffffffu, v, o);
    if ((threadIdx.x & 31) == 0) red[threadIdx.x >> 5] = v;
    __syncthreads();
    float s = 0.f;
    if (threadIdx.x < 6) s = red[threadIdx.x];
    if (threadIdx.x < 32) {
        s += __shfl_xor_sync(0xffffffffu, s, 4);
        s += __shfl_xor_sync(0xffffffffu, s, 2);
        s += __shfl_xor_sync(0xffffffffu, s, 1);
        if (threadIdx.x == 0) red[0] = s;
    }
    __syncthreads();
    float r = red[0];
    __syncthreads();
    return r;
}

// radial basis in registers
__device__ __forceinline__ void radial_eval(float d, float* R) {
    const float invs = 1.f / 0.28f;
    #pragma unroll
    for (int r = 0; r < 16; r++) {
        float c = 0.8f + 0.28f * (float)r;
        float tt = (d - c) * invs;
        R[r] = __expf(-tt * tt);
    }
}

// thread-local MLP: u[UR] -> w[16], weights in smem (float4 broadcast)
template<int UR>
__device__ __forceinline__ void mlp_eval(const float* u,
                                         const float4* s_pw1, const float* s_b1,
                                         const float4* s_pw2, const float* s_b2,
                                         float* w) {
    float h[32];
    #pragma unroll
    for (int j = 0; j < 32; j++) h[j] = s_b1[j];
    #pragma unroll
    for (int r = 0; r < UR; r++) {
        float uv = u[r];
        #pragma unroll
        for (int j4 = 0; j4 < 8; j4++) {
            float4 p = s_pw1[r * 8 + j4];
            h[4*j4+0] += uv * p.x; h[4*j4+1] += uv * p.y;
            h[4*j4+2] += uv * p.z; h[4*j4+3] += uv * p.w;
        }
    }
    #pragma unroll
    for (int j = 0; j < 32; j++) h[j] = h[j] / (1.f + __expf(-h[j]));
    #pragma unroll
    for (int d = 0; d < 16; d++) w[d] = s_b2[d];
    #pragma unroll
    for (int j = 0; j < 32; j++) {
        float hv = h[j];
        #pragma unroll
        for (int d4 = 0; d4 < 4; d4++) {
            float4 p = s_pw2[j * 4 + d4];
            w[4*d4+0] += hv * p.x; w[4*d4+1] += hv * p.y;
            w[4*d4+2] += hv * p.z; w[4*d4+3] += hv * p.w;
        }
    }
}

// ---------------- node embedding (+ zero mi, Vi for layer 0) ----------------
__global__ void node_embed_kernel(const int* __restrict__ species,
                                  const float* __restrict__ zt,
                                  const float* __restrict__ wsp) {
    __shared__ float sZ[16];
    __shared__ float red[8];
    int n = blockIdx.x;
    int t = threadIdx.x;
    if (t < DIM) g_mi[(ll)n * DIM + t] = 0.f;
    if (t < 64)  g_Vi[n * 64 + t] = 0.f;
    if (t < 16) sZ[t] = zt[species[n] * 16 + t];
    __syncthreads();
    float val = 0.f;
    if (t < DIM) {
        #pragma unroll
        for (int z = 0; z < 16; z++) val += sZ[z] * wsp[z * DIM + t];
    }
    float mu = block_sum_192(val, red) * (1.f / DIM);
    float dx = (t < DIM) ? (val - mu) : 0.f;
    float var = block_sum_192(dx * dx, red) * (1.f / DIM);
    if (t < DIM) g_xi[n * DIM + t] = dx * rsqrtf(var + 1e-6f);
}

// ---------------- edge geometry + fused layer-0 MLP (switch folded) ----------------
__global__ __launch_bounds__(256) void edge_geom_kernel(
    const float* __restrict__ dist, const float* __restrict__ vec,
    const float* __restrict__ swtch,
    const float* __restrict__ pw1, const float* __restrict__ pb1,
    const float* __restrict__ pw2, const float* __restrict__ pb2)
{
    __shared__ float4 s_pw1[128];   // 16x32
    __shared__ float4 s_pw2[128];   // 32x16
    __shared__ float  s_b1[32];
    __shared__ float  s_b2[16];
    int tid = threadIdx.x;
    for (int i = tid; i < 128; i += 256) {
        s_pw1[i] = reinterpret_cast<const float4*>(pw1)[i];
        s_pw2[i] = reinterpret_cast<const float4*>(pw2)[i];
    }
    if (tid < 32) s_b1[tid] = pb1[tid];
    if (tid < 16) s_b2[tid] = pb2[tid];
    __syncthreads();

    int e = blockIdx.x * blockDim.x + tid;
    if (e >= EE) return;
    float d = dist[e];
    float inv = 1.f / d;
    float x = vec[e * 3 + 0] * inv;
    float y = vec[e * 3 + 1] * inv;
    float z = vec[e * 3 + 2] * inv;
    const float s3  = 1.7320508075688772f;
    const float s15 = 3.872983346207417f;
    const float c1  = 0.7905694150420949f;
    const float c2  = 0.6123724356957945f;
    float x2 = x * x, y2 = y * y, z2 = z * z;
    float Y[16];
    Y[0]  = 1.f;
    Y[1]  = x; Y[2] = y; Y[3] = z;
    Y[4]  = s3 * x * y;
    Y[5]  = s3 * y * z;
    Y[6]  = 0.5f * (3.f * z2 - 1.f);
    Y[7]  = s3 * x * z;
    Y[8]  = 0.5f * s3 * (x2 - y2);
    Y[9]  = c1 * y * (3.f * x2 - y2);
    Y[10] = s15 * x * y * z;
    Y[11] = c2 * y * (5.f * z2 - 1.f);
    Y[12] = 0.5f * z * (5.f * z2 - 3.f);
    Y[13] = c2 * x * (5.f * z2 - 1.f);
    Y[14] = 0.5f * s15 * z * (x2 - y2);
    Y[15] = c1 * x * (x2 - 3.f * y2);
    float R[16];
    radial_eval(d, R);
    float4* yo = reinterpret_cast<float4*>(g_Y + e * 16);
    #pragma unroll
    for (int i = 0; i < 4; i++)
        yo[i] = make_float4(Y[4*i], Y[4*i+1], Y[4*i+2], Y[4*i+3]);
    float w[16];
    mlp_eval<16>(R, s_pw1, s_b1, s_pw2, s_b2, w);
    float sws = swtch[e] * 0.25f;
    float4* wp = reinterpret_cast<float4*>(g_w + (ll)e * 16);
    #pragma unroll
    for (int d4 = 0; d4 < 4; d4++)
        wp[d4] = make_float4(w[4*d4] * sws, w[4*d4+1] * sws, w[4*d4+2] * sws, w[4*d4+3] * sws);
}

// ---------------- fused layer-1 ur gather + MLP (parallel phase A) ----------------
#define U2PAD 264
__global__ __launch_bounds__(256) void ur1mlp1_kernel(
    const int* __restrict__ src, const int* __restrict__ dst,
    const float* __restrict__ dist, const float* __restrict__ swtch,
    const float* __restrict__ pw1, const float* __restrict__ pb1,
    const float* __restrict__ pw2, const float* __restrict__ pb2)
{
    __shared__ float4 s_pw1[256];   // 32x32
    __shared__ float4 s_pw2[128];   // 32x16
    __shared__ float  s_b1[32];
    __shared__ float  s_b2[16];
    __shared__ float  s_u2[16][U2PAD];

    int tid = threadIdx.x;
    for (int i = tid; i < 256; i += 256) s_pw1[i] = reinterpret_cast<const float4*>(pw1)[i];
    for (int i = tid; i < 128; i += 256) s_pw2[i] = reinterpret_cast<const float4*>(pw2)[i];
    if (tid < 32) s_b1[tid] = pb1[tid];
    if (tid < 16) s_b2[tid] = pb2[tid];
    __syncthreads();

    int wid = tid >> 5, lane = tid & 31;
    int base = blockIdx.x * 256;
    int tap = lane & 3;
    int eo  = lane >> 2;   // 0..7

    #pragma unroll
    for (int it = 0; it < 4; it++) {
        int e_loc = wid * 32 + it * 8 + eo;
        int e = base + e_loc;
        if (e < EE) {
            int is = src[e], id = dst[e];
            const float4* Yp = reinterpret_cast<const float4*>(g_Y + e * 16);
            float Yv[16];
            #pragma unroll
            for (int q = 0; q < 4; q++) {
                float4 y4 = Yp[q];
                Yv[4*q]=y4.x; Yv[4*q+1]=y4.y; Yv[4*q+2]=y4.z; Yv[4*q+3]=y4.w;
            }
            const float4* Vd4 = reinterpret_cast<const float4*>(&g_Vi[(ll)id * 64 + tap * 16]);
            const float4* Vs4 = reinterpret_cast<const float4*>(&g_Vi[(ll)is * 64 + tap * 16]);
            float Vd[16], Vs[16];
            #pragma unroll
            for (int q = 0; q < 4; q++) {
                float4 a4 = Vd4[q], b4 = Vs4[q];
                Vd[4*q]=a4.x; Vd[4*q+1]=a4.y; Vd[4*q+2]=a4.z; Vd[4*q+3]=a4.w;
                Vs[4*q]=b4.x; Vs[4*q+1]=b4.y; Vs[4*q+2]=b4.z; Vs[4*q+3]=b4.w;
            }
            float u0 = (Vd[0] + Vs[0]) * Yv[0];
            float u1 = 0.f, u2 = 0.f, u3 = 0.f;
            #pragma unroll
            for (int m = 1; m < 4; m++)  u1 += (Vd[m] - Vs[m]) * Yv[m];
            #pragma unroll
            for (int m = 4; m < 9; m++)  u2 += (Vd[m] + Vs[m]) * Yv[m];
            #pragma unroll
            for (int m = 9; m < 16; m++) u3 += (Vd[m] - Vs[m]) * Yv[m];
            s_u2[ 0 + tap][e_loc] = u0;
            s_u2[ 4 + tap][e_loc] = u1;
            s_u2[ 8 + tap][e_loc] = u2;
            s_u2[12 + tap][e_loc] = u3;
        }
    }
    __syncthreads();

    int e = base + tid;
    if (e >= EE) return;
    float u[32];
    radial_eval(dist[e], u);
    #pragma unroll
    for (int j = 0; j < 16; j++) u[16 + j] = s_u2[j][tid];
    float w[16];
    mlp_eval<32>(u, s_pw1, s_b1, s_pw2, s_b2, w);
    float sws = swtch[e] * 0.25f;
    float4* wp = reinterpret_cast<float4*>(g_w + (ll)e * 16);
    #pragma unroll
    for (int d4 = 0; d4 < 4; d4++)
        wp[d4] = make_float4(w[4*d4] * sws, w[4*d4+1] * sws, w[4*d4+2] * sws, w[4*d4+3] * sws);
}

// ---------------- QKV SGEMM (double-buffered, plain-A smem, fp16 q/k out) ----------------
__global__ __launch_bounds__(256, 2) void sgemm_qkv_kernel(
    const float* __restrict__ wq, const float* __restrict__ wk,
    const float* __restrict__ wv)
{
    __shared__ float As[2][16][128];
    __shared__ float Bs[2][16][128];
    int tid = threadIdx.x;
    int tx = tid & 15, ty = tid >> 4;
    int row0 = blockIdx.y * 128;
    int col0 = blockIdx.x * 128;
    u64 acc[8][4];
    #pragma unroll
    for (int i = 0; i < 8; i++)
        #pragma unroll
        for (int j = 0; j < 4; j++) acc[i][j] = 0ull;

    const int ar = tid >> 1;
    const int ac0 = (tid & 1) * 8;
    const int agrow = row0 + ar;
    const int bbr = tid >> 4;
    const int bbc = (tid & 15) * 8;
    const int bgcol = col0 + bbc;

    float4 pa0, pa1, pb0, pb1;
    {
        pa0 = make_float4(0,0,0,0); pa1 = make_float4(0,0,0,0);
        if (agrow < NN) {
            const float* s = g_xi + (ll)agrow * DIM + ac0;
            pa0 = *reinterpret_cast<const float4*>(s);
            pa1 = *reinterpret_cast<const float4*>(s + 4);
        }
        pb0 = make_float4(0,0,0,0); pb1 = make_float4(0,0,0,0);
        if (bgcol < QKVW) {
            const float* srcp; int c;
            if (bgcol < 320)      { srcp = wq + (ll)bbr * 320; c = bgcol; }
            else if (bgcol < 640) { srcp = wk + (ll)bbr * 320; c = bgcol - 320; }
            else                  { srcp = wv + (ll)bbr * 176; c = bgcol - 640; }
            pb0 = *reinterpret_cast<const float4*>(srcp + c);
            pb1 = *reinterpret_cast<const float4*>(srcp + c + 4);
        }
        As[0][ac0+0][ar] = pa0.x;
        As[0][ac0+1][ar] = pa0.y;
        As[0][ac0+2][ar] = pa0.z;
        As[0][ac0+3][ar] = pa0.w;
        As[0][ac0+4][ar] = pa1.x;
        As[0][ac0+5][ar] = pa1.y;
        As[0][ac0+6][ar] = pa1.z;
        As[0][ac0+7][ar] = pa1.w;
        *reinterpret_cast<float4*>(&Bs[0][bbr][bbc])     = pb0;
        *reinterpret_cast<float4*>(&Bs[0][bbr][bbc + 4]) = pb1;
    }
    __syncthreads();

    for (int kt = 0; kt < 11; ++kt) {
        int cur = kt & 1, nxt = cur ^ 1;
        bool has_nxt = (kt + 1 < 11);
        if (has_nxt) {
            int gkbase = (kt + 1) * 16;
            pa0 = make_float4(0,0,0,0); pa1 = make_float4(0,0,0,0);
            if (agrow < NN) {
                const float* s = g_xi + (ll)agrow * DIM + gkbase + ac0;
                pa0 = *reinterpret_cast<const float4*>(s);
                pa1 = *reinterpret_cast<const float4*>(s + 4);
            }
            int gk = gkbase + bbr;
            pb0 = make_float4(0,0,0,0); pb1 = make_float4(0,0,0,0);
            if (bgcol < QKVW) {
                const float* srcp; int c;
                if (bgcol < 320)      { srcp = wq + (ll)gk * 320; c = bgcol; }
                else if (bgcol < 640) { srcp = wk + (ll)gk * 320; c = bgcol - 320; }
                else                  { srcp = wv + (ll)gk * 176; c = bgcol - 640; }
                pb0 = *reinterpret_cast<const float4*>(srcp + c);
                pb1 = *reinterpret_cast<const float4*>(srcp + c + 4);
            }
        }
        #pragma unroll
        for (int k = 0; k < 16; ++k) {
            const float4* ap = reinterpret_cast<const float4*>(&As[cur][k][ty * 8]);
            float4 af0 = ap[0], af1 = ap[1];
            u64 a[8];
            a[0] = pack2(af0.x, af0.x); a[1] = pack2(af0.y, af0.y);
            a[2] = pack2(af0.z, af0.z); a[3] = pack2(af0.w, af0.w);
            a[4] = pack2(af1.x, af1.x); a[5] = pack2(af1.y, af1.y);
            a[6] = pack2(af1.z, af1.z); a[7] = pack2(af1.w, af1.w);
            u64 b[4];
            {
                const ulonglong2* p = reinterpret_cast<const ulonglong2*>(&Bs[cur][k][tx * 8]);
                ulonglong2 w0 = p[0], w1 = p[1];
                b[0]=w0.x; b[1]=w0.y; b[2]=w1.x; b[3]=w1.y;
            }
            #pragma unroll
            for (int i = 0; i < 8; i++)
                #pragma unroll
                for (int j = 0; j < 4; j++)
                    fma2(acc[i][j], a[i], b[j]);
        }
        if (has_nxt) {
            As[nxt][ac0+0][ar] = pa0.x;
            As[nxt][ac0+1][ar] = pa0.y;
            As[nxt][ac0+2][ar] = pa0.z;
            As[nxt][ac0+3][ar] = pa0.w;
            As[nxt][ac0+4][ar] = pa1.x;
            As[nxt][ac0+5][ar] = pa1.y;
            As[nxt][ac0+6][ar] = pa1.z;
            As[nxt][ac0+7][ar] = pa1.w;
            *reinterpret_cast<float4*>(&Bs[nxt][bbr][bbc])     = pb0;
            *reinterpret_cast<float4*>(&Bs[nxt][bbr][bbc + 4]) = pb1;
            __syncthreads();
        }
    }
    #pragma unroll
    for (int i = 0; i < 8; i++) {
        int gr = row0 + ty * 8 + i;
        if (gr >= NN) continue;
        #pragma unroll
        for (int j = 0; j < 4; j++) {
            int gc = col0 + tx * 8 + j * 2;
            if (gc < QKVW) {
                float2 f = unpack2(acc[i][j]);
                if (gc < 640) {
                    int blk = (gc < 320) ? 0 : 320;
                    int c = gc - blk;
                    int h = c >> 4, d = c & 15;
                    int oc = blk + ((d >> 2) * 20 + h) * 4 + (d & 3);  // pair-preserving (d even)
                    __half2 hv = __floats2half2_rn(f.x, f.y);
                    *reinterpret_cast<__half2*>(&g_qkh[(ll)gr * 640 + oc]) = hv;
                } else {
                    *reinterpret_cast<float2*>(&g_v[(ll)gr * DIM + (gc - 640)]) = f;
                }
            }
        }
    }
}

// ---------------- update SGEMM (double-buffered, plain-A smem): G = [xi|mi] @ uw ----------------
__global__ __launch_bounds__(256, 2) void sgemm_upd_kernel(const float* __restrict__ B)
{
    __shared__ float As[2][16][128];
    __shared__ float Bs[2][16][128];
    int tid = threadIdx.x;
    int tx = tid & 15, ty = tid >> 4;
    int row0 = blockIdx.y * 128;
    int col0 = blockIdx.x * 128;
    u64 acc[8][4];
    #pragma unroll
    for (int i = 0; i < 8; i++)
        #pragma unroll
        for (int j = 0; j < 4; j++) acc[i][j] = 0ull;

    const int ar = tid >> 1;
    const int ac0 = (tid & 1) * 8;
    const int agrow = row0 + ar;
    const int bbr = tid >> 4;
    const int bbc = (tid & 15) * 8;
    const int bgcol = col0 + bbc;

    float4 pa0, pa1, pb0, pb1;
    {
        pa0 = make_float4(0,0,0,0); pa1 = make_float4(0,0,0,0);
        if (agrow < NN) {
            const float* s = g_xi + (ll)agrow * DIM + ac0;
            pa0 = *reinterpret_cast<const float4*>(s);
            pa1 = *reinterpret_cast<const float4*>(s + 4);
        }
        pb0 = make_float4(0,0,0,0); pb1 = make_float4(0,0,0,0);
        if (bgcol < DIM) {
            const float* s = B + (ll)bbr * DIM + bgcol;
            pb0 = *reinterpret_cast<const float4*>(s);
            pb1 = *reinterpret_cast<const float4*>(s + 4);
        }
        As[0][ac0+0][ar] = pa0.x;
        As[0][ac0+1][ar] = pa0.y;
        As[0][ac0+2][ar] = pa0.z;
        As[0][ac0+3][ar] = pa0.w;
        As[0][ac0+4][ar] = pa1.x;
        As[0][ac0+5][ar] = pa1.y;
        As[0][ac0+6][ar] = pa1.z;
        As[0][ac0+7][ar] = pa1.w;
        *reinterpret_cast<float4*>(&Bs[0][bbr][bbc])     = pb0;
        *reinterpret_cast<float4*>(&Bs[0][bbr][bbc + 4]) = pb1;
    }
    __syncthreads();

    for (int kt = 0; kt < 22; ++kt) {
        int cur = kt & 1, nxt = cur ^ 1;
        bool has_nxt = (kt + 1 < 22);
        if (has_nxt) {
            int gkbase = (kt + 1) * 16;
            const float* Ap = (gkbase < DIM) ? g_xi : g_mi;
            int koff = (gkbase < DIM) ? gkbase : gkbase - DIM;
            pa0 = make_float4(0,0,0,0); pa1 = make_float4(0,0,0,0);
            if (agrow < NN) {
                const float* s = Ap + (ll)agrow * DIM + koff + ac0;
                pa0 = *reinterpret_cast<const float4*>(s);
                pa1 = *reinterpret_cast<const float4*>(s + 4);
            }
            int gk = gkbase + bbr;
            pb0 = make_float4(0,0,0,0); pb1 = make_float4(0,0,0,0);
            if (bgcol < DIM) {
                const float* s = B + (ll)gk * DIM + bgcol;
                pb0 = *reinterpret_cast<const float4*>(s);
                pb1 = *reinterpret_cast<const float4*>(s + 4);
            }
        }
        #pragma unroll
        for (int k = 0; k < 16; ++k) {
            const float4* ap = reinterpret_cast<const float4*>(&As[cur][k][ty * 8]);
            float4 af0 = ap[0], af1 = ap[1];
            u64 a[8];
            a[0] = pack2(af0.x, af0.x); a[1] = pack2(af0.y, af0.y);
            a[2] = pack2(af0.z, af0.z); a[3] = pack2(af0.w, af0.w);
            a[4] = pack2(af1.x, af1.x); a[5] = pack2(af1.y, af1.y);
            a[6] = pack2(af1.z, af1.z); a[7] = pack2(af1.w, af1.w);
            u64 b[4];
            {
                const ulonglong2* p = reinterpret_cast<const ulonglong2*>(&Bs[cur][k][tx * 8]);
                ulonglong2 w0 = p[0], w1 = p[1];
                b[0]=w0.x; b[1]=w0.y; b[2]=w1.x; b[3]=w1.y;
            }
            #pragma unroll
            for (int i = 0; i < 8; i++)
                #pragma unroll
                for (int j = 0; j < 4; j++)
                    fma2(acc[i][j], a[i], b[j]);
        }
        if (has_nxt) {
            As[nxt][ac0+0][ar] = pa0.x;
            As[nxt][ac0+1][ar] = pa0.y;
            As[nxt][ac0+2][ar] = pa0.z;
            As[nxt][ac0+3][ar] = pa0.w;
            As[nxt][ac0+4][ar] = pa1.x;
            As[nxt][ac0+5][ar] = pa1.y;
            As[nxt][ac0+6][ar] = pa1.z;
            As[nxt][ac0+7][ar] = pa1.w;
            *reinterpret_cast<float4*>(&Bs[nxt][bbr][bbc])     = pb0;
            *reinterpret_cast<float4*>(&Bs[nxt][bbr][bbc + 4]) = pb1;
            __syncthreads();
        }
    }
    #pragma unroll
    for (int i = 0; i < 8; i++) {
        int gr = row0 + ty * 8 + i;
        if (gr >= NN) continue;
        #pragma unroll
        for (int j = 0; j < 4; j++) {
            int gc = col0 + tx * 8 + j * 2;
            if (gc < DIM) {
                float2 f = unpack2(acc[i][j]);
                *reinterpret_cast<float2*>(&g_G[(ll)gr * DIM + gc]) = f;
            }
        }
    }
}

// ---------------- slim edge attention + scatter (fp16 q/k, HMUL2 products) ----------------
template<int LAYER>
__global__ __launch_bounds__(256) void edge_attn_kernel(
    const int* __restrict__ src, const int* __restrict__ dst)
{
    __shared__ float s_a[8][20];

    int tid = threadIdx.x;
    int wid = tid >> 5, lane = tid & 31;
    int b0a = 4 * lane;
    int b0b = 4 * (lane + 32);
    int hA0 =  b0a      / VD, hA1 = (b0a + 1) / VD, hA2 = (b0a + 2) / VD, hA3 = (b0a + 3) / VD;
    int hB0 =  b0b      / VD, hB1 = (b0b + 1) / VD, hB2 = (b0b + 2) / VD, hB3 = (b0b + 3) / VD;

    for (int e = blockIdx.x * 8 + wid; e < EE; e += gridDim.x * 8) {
        int is = src[e], id = dst[e];
        float4 y4;
        if (LAYER == 0 && lane < 16)
            y4 = __ldg(reinterpret_cast<const float4*>(g_Y) + e * 4 + (lane & 3));
        const uint2* qh = reinterpret_cast<const uint2*>(g_qkh + (ll)id * 640);
        const uint2* kh = reinterpret_cast<const uint2*>(g_qkh + (ll)is * 640 + 320);
        const float4* wp = reinterpret_cast<const float4*>(g_w + (ll)e * 16);
        // hoist v loads (independent of s_a) — overlap L2 latency with logit FMAs
        const float* vr = g_v + (ll)is * DIM;
        float4 v4a = *reinterpret_cast<const float4*>(vr + b0a);
        float4 v4b = make_float4(0, 0, 0, 0);
        if (lane < 12) v4b = *reinterpret_cast<const float4*>(vr + b0b);
        if (lane < 20) {
            float a0 = 0.f, a1 = 0.f;
            #pragma unroll
            for (int d4 = 0; d4 < 4; d4++) {
                uint2 qu = __ldg(qh + d4 * 20 + lane);
                uint2 ku = __ldg(kh + d4 * 20 + lane);
                float4 w4 = __ldg(wp + d4);
                __half2 p0 = __hmul2(*reinterpret_cast<__half2*>(&qu.x),
                                     *reinterpret_cast<__half2*>(&ku.x));
                __half2 p1 = __hmul2(*reinterpret_cast<__half2*>(&qu.y),
                                     *reinterpret_cast<__half2*>(&ku.y));
                float2 f0 = __half22float2(p0);
                float2 f1 = __half22float2(p1);
                a0 += f0.x * w4.x + f0.y * w4.y;
                a1 += f1.x * w4.z + f1.y * w4.w;
            }
            s_a[wid][lane] = a0 + a1;
        }
        __syncwarp();
        float* mr = &g_mi[(ll)id * DIM];
        {
            float4 o;
            o.x = s_a[wid][hA0] * v4a.x;
            o.y = s_a[wid][hA1] * v4a.y;
            o.z = s_a[wid][hA2] * v4a.z;
            o.w = s_a[wid][hA3] * v4a.w;
            atomicAdd(reinterpret_cast<float4*>(mr + b0a), o);
        }
        if (lane < 12) {
            float4 o;
            o.x = s_a[wid][hB0] * v4b.x;
            o.y = s_a[wid][hB1] * v4b.y;
            o.z = s_a[wid][hB2] * v4b.z;
            o.w = s_a[wid][hB3] * v4b.w;
            atomicAdd(reinterpret_cast<float4*>(mr + b0b), o);
        }
        if (LAYER == 0) {
            if (lane < 16) {
                float at = s_a[wid][16 + (lane >> 2)];
                float4 o = make_float4(at * y4.x, at * y4.y, at * y4.z, at * y4.w);
                atomicAdd(reinterpret_cast<float4*>(&g_Vi[(ll)id * 64 + 4 * lane]), o);
            }
        }
        __syncwarp();
    }
}

// ---------------- residual + LayerNorm (+ zero mi for next layer) ----------------
__global__ void resln_kernel(const float* __restrict__ ub, float* __restrict__ out, int toXi) {
    __shared__ float red[8];
    int n = blockIdx.x, t = threadIdx.x;
    float val = 0.f;
    if (t < DIM) val = g_xi[n * DIM + t] + g_G[n * DIM + t] + ub[t];
    float mu = block_sum_192(val, red) * (1.f / DIM);
    float dx = (t < DIM) ? (val - mu) : 0.f;
    float var = block_sum_192(dx * dx, red) * (1.f / DIM);
    if (t < DIM) {
        float o = dx * rsqrtf(var + 1e-6f);
        if (toXi) {
            g_xi[n * DIM + t] = o;
            g_mi[(ll)n * DIM + t] = 0.f;
        } else {
            out[n * DIM + t] = o;
        }
    }
}

// ---------------- launch ----------------
extern "C" void kernel_launch(void* const* d_in, const int* in_sizes, int n_in,
                              void* d_out, int out_size) {
    const int*   species  = (const int*)  d_in[0];
    const float* dist     = (const float*)d_in[1];
    const float* swtch    = (const float*)d_in[2];
    const int*   esrc     = (const int*)  d_in[3];
    const int*   edst     = (const int*)  d_in[4];
    const float* vec      = (const float*)d_in[5];
    const float* z_table  = (const float*)d_in[6];
    const float* w_sp     = (const float*)d_in[7];
    const float* pw1_0    = (const float*)d_in[8];
    const float* pb1_0    = (const float*)d_in[9];
    const float* pw2_0    = (const float*)d_in[10];
    const float* pb2_0    = (const float*)d_in[11];
    const float* wq_0     = (const float*)d_in[12];
    const float* wk_0     = (const float*)d_in[13];
    const float* wv_0     = (const float*)d_in[14];
    const float* uw_0     = (const float*)d_in[15];
    const float* ub_0     = (const float*)d_in[16];
    const float* pw1_1    = (const float*)d_in[17];
    const float* pb1_1    = (const float*)d_in[18];
    const float* pw2_1    = (const float*)d_in[19];
    const float* pb2_1    = (const float*)d_in[20];
    const float* wq_1     = (const float*)d_in[21];
    const float* wk_1     = (const float*)d_in[22];
    const float* wv_1     = (const float*)d_in[23];
    const float* uw_1     = (const float*)d_in[24];
    const float* ub_1     = (const float*)d_in[25];
    float* out = (float*)d_out;

    const int EB  = (EE + 255) / 256;
    const int EWB = 740;   // 5 blocks/SM x 148 SMs — fully resident persistent grid
    dim3 grid_qkv(7, 79);
    dim3 grid_upd(2, 79);

    node_embed_kernel<<<NN, 192>>>(species, z_table, w_sp);                            // 0
    edge_geom_kernel<<<EB, 256>>>(dist, vec, swtch, pw1_0, pb1_0, pw2_0, pb2_0);       // 1

    // ---- layer 0 ----
    sgemm_qkv_kernel<<<grid_qkv, 256>>>(wq_0, wk_0, wv_0);                             // 2
    edge_attn_kernel<0><<<EWB, 256>>>(esrc, edst);                                     // 3 (profiled)
    sgemm_upd_kernel<<<grid_upd, 256>>>(uw_0);                                         // 4
    resln_kernel<<<NN, 192>>>(ub_0, out, 1);                                           // 5

    // ---- layer 1 ----
    ur1mlp1_kernel<<<EB, 256>>>(esrc, edst, dist, swtch, pw1_1, pb1_1, pw2_1, pb2_1);  // 6
    sgemm_qkv_kernel<<<grid_qkv, 256>>>(wq_1, wk_1, wv_1);                             // 7
    edge_attn_kernel<1><<<EWB, 256>>>(esrc, edst);                                     // 8
    sgemm_upd_kernel<<<grid_upd, 256>>>(uw_1);                                         // 9
    resln_kernel<<<NN, 192>>>(ub_1, out, 0);                                           // 10
}

// round 17
// speedup vs baseline: 1.2735x; 1.2735x over previous
#include <cuda_runtime.h>
#include <cuda_fp16.h>
#include <math.h>

#define NN   10000
#define EE   320000
#define DIM  176
#define ATT  16
#define SHH  16
#define THH  4
#define NHH  20
#define VD   11
#define NSPH 16
#define RDIMC 16
#define QKVW 816   // 320 + 320 + 176 (GEMM column space)

typedef unsigned long long u64;
typedef long long ll;
typedef unsigned int u32;

// ---------------- scratch ----------------
__device__ float  g_xi [NN * DIM];
__device__ __half g_qkh[NN * 640];   // per node: qT[320 half] | kT[320 half], head-transposed
__device__ float  g_v  [NN * DIM];   // per node: v[176] fp32
__device__ float  g_mi [NN * DIM];
__device__ float  g_Vi [NN * THH * NSPH];
__device__ float  g_Y  [EE * NSPH];
__device__ float  g_G  [NN * DIM];
__device__ float  g_w  [(ll)EE * 16];   // per-edge MLP output (switch-scaled)

// ---------------- helpers ----------------
__device__ __forceinline__ u64 pack2(float x, float y) {
    u64 r; asm("mov.b64 %0,{%1,%2};" : "=l"(r) : "f"(x), "f"(y)); return r;
}
__device__ __forceinline__ void fma2(u64& d, u64 a, u64 b) {
    asm("fma.rn.f32x2 %0, %1, %2, %3;" : "=l"(d) : "l"(a), "l"(b), "l"(d));
}
__device__ __forceinline__ float2 unpack2(u64 v) {
    float2 f; asm("mov.b64 {%0,%1},%2;" : "=f"(f.x), "=f"(f.y) : "l"(v)); return f;
}

__device__ __forceinline__ void mma16816(float* d,
                                         const u32* a, const u32* b,
                                         const float* c) {
    asm volatile(
        "mma.sync.aligned.m16n8k16.row.col.f32.f16.f16.f32 "
        "{%0,%1,%2,%3}, {%4,%5,%6,%7}, {%8,%9}, {%10,%11,%12,%13};\n"
        : "=f"(d[0]), "=f"(d[1]), "=f"(d[2]), "=f"(d[3])
        : "r"(a[0]), "r"(a[1]), "r"(a[2]), "r"(a[3]),
          "r"(b[0]), "r"(b[1]),
          "f"(c[0]), "f"(c[1]), "f"(c[2]), "f"(c[3]));
}

__device__ __forceinline__ float block_sum_192(float v, float* red) {
    #pragma unroll
    for (int o = 16; o; o >>= 1) v += __shfl_xor_sync(0xffffffffu, v, o);
    if ((threadIdx.x & 31) == 0) red[threadIdx.x >> 5] = v;
    __syncthreads();
    float s = 0.f;
    if (threadIdx.x < 6) s = red[threadIdx.x];
    if (threadIdx.x < 32) {
        s += __shfl_xor_sync(0xffffffffu, s, 4);
        s += __shfl_xor_sync(0xffffffffu, s, 2);
        s += __shfl_xor_sync(0xffffffffu, s, 1);
        if (threadIdx.x == 0) red[0] = s;
    }
    __syncthreads();
    float r = red[0];
    __syncthreads();
    return r;
}

// radial basis in registers
__device__ __forceinline__ void radial_eval(float d, float* R) {
    const float invs = 1.f / 0.28f;
    #pragma unroll
    for (int r = 0; r < 16; r++) {
        float c = 0.8f + 0.28f * (float)r;
        float tt = (d - c) * invs;
        R[r] = __expf(-tt * tt);
    }
}

// thread-local MLP: u[UR] -> w[16], weights in smem (float4 broadcast)
template<int UR>
__device__ __forceinline__ void mlp_eval(const float* u,
                                         const float4* s_pw1, const float* s_b1,
                                         const float4* s_pw2, const float* s_b2,
                                         float* w) {
    float h[32];
    #pragma unroll
    for (int j = 0; j < 32; j++) h[j] = s_b1[j];
    #pragma unroll
    for (int r = 0; r < UR; r++) {
        float uv = u[r];
        #pragma unroll
        for (int j4 = 0; j4 < 8; j4++) {
            float4 p = s_pw1[r * 8 + j4];
            h[4*j4+0] += uv * p.x; h[4*j4+1] += uv * p.y;
            h[4*j4+2] += uv * p.z; h[4*j4+3] += uv * p.w;
        }
    }
    #pragma unroll
    for (int j = 0; j < 32; j++) h[j] = h[j] / (1.f + __expf(-h[j]));
    #pragma unroll
    for (int d = 0; d < 16; d++) w[d] = s_b2[d];
    #pragma unroll
    for (int j = 0; j < 32; j++) {
        float hv = h[j];
        #pragma unroll
        for (int d4 = 0; d4 < 4; d4++) {
            float4 p = s_pw2[j * 4 + d4];
            w[4*d4+0] += hv * p.x; w[4*d4+1] += hv * p.y;
            w[4*d4+2] += hv * p.z; w[4*d4+3] += hv * p.w;
        }
    }
}

// ---------------- node embedding (+ zero mi, Vi for layer 0) ----------------
__global__ void node_embed_kernel(const int* __restrict__ species,
                                  const float* __restrict__ zt,
                                  const float* __restrict__ wsp) {
    __shared__ float sZ[16];
    __shared__ float red[8];
    int n = blockIdx.x;
    int t = threadIdx.x;
    if (t < DIM) g_mi[(ll)n * DIM + t] = 0.f;
    if (t < 64)  g_Vi[n * 64 + t] = 0.f;
    if (t < 16) sZ[t] = zt[species[n] * 16 + t];
    __syncthreads();
    float val = 0.f;
    if (t < DIM) {
        #pragma unroll
        for (int z = 0; z < 16; z++) val += sZ[z] * wsp[z * DIM + t];
    }
    float mu = block_sum_192(val, red) * (1.f / DIM);
    float dx = (t < DIM) ? (val - mu) : 0.f;
    float var = block_sum_192(dx * dx, red) * (1.f / DIM);
    if (t < DIM) g_xi[n * DIM + t] = dx * rsqrtf(var + 1e-6f);
}

// ---------------- edge geometry + fused layer-0 MLP (switch folded) ----------------
__global__ __launch_bounds__(256) void edge_geom_kernel(
    const float* __restrict__ dist, const float* __restrict__ vec,
    const float* __restrict__ swtch,
    const float* __restrict__ pw1, const float* __restrict__ pb1,
    const float* __restrict__ pw2, const float* __restrict__ pb2)
{
    __shared__ float4 s_pw1[128];   // 16x32
    __shared__ float4 s_pw2[128];   // 32x16
    __shared__ float  s_b1[32];
    __shared__ float  s_b2[16];
    int tid = threadIdx.x;
    for (int i = tid; i < 128; i += 256) {
        s_pw1[i] = reinterpret_cast<const float4*>(pw1)[i];
        s_pw2[i] = reinterpret_cast<const float4*>(pw2)[i];
    }
    if (tid < 32) s_b1[tid] = pb1[tid];
    if (tid < 16) s_b2[tid] = pb2[tid];
    __syncthreads();

    int e = blockIdx.x * blockDim.x + tid;
    if (e >= EE) return;
    float d = dist[e];
    float inv = 1.f / d;
    float x = vec[e * 3 + 0] * inv;
    float y = vec[e * 3 + 1] * inv;
    float z = vec[e * 3 + 2] * inv;
    const float s3  = 1.7320508075688772f;
    const float s15 = 3.872983346207417f;
    const float c1  = 0.7905694150420949f;
    const float c2  = 0.6123724356957945f;
    float x2 = x * x, y2 = y * y, z2 = z * z;
    float Y[16];
    Y[0]  = 1.f;
    Y[1]  = x; Y[2] = y; Y[3] = z;
    Y[4]  = s3 * x * y;
    Y[5]  = s3 * y * z;
    Y[6]  = 0.5f * (3.f * z2 - 1.f);
    Y[7]  = s3 * x * z;
    Y[8]  = 0.5f * s3 * (x2 - y2);
    Y[9]  = c1 * y * (3.f * x2 - y2);
    Y[10] = s15 * x * y * z;
    Y[11] = c2 * y * (5.f * z2 - 1.f);
    Y[12] = 0.5f * z * (5.f * z2 - 3.f);
    Y[13] = c2 * x * (5.f * z2 - 1.f);
    Y[14] = 0.5f * s15 * z * (x2 - y2);
    Y[15] = c1 * x * (x2 - 3.f * y2);
    float R[16];
    radial_eval(d, R);
    float4* yo = reinterpret_cast<float4*>(g_Y + e * 16);
    #pragma unroll
    for (int i = 0; i < 4; i++)
        yo[i] = make_float4(Y[4*i], Y[4*i+1], Y[4*i+2], Y[4*i+3]);
    float w[16];
    mlp_eval<16>(R, s_pw1, s_b1, s_pw2, s_b2, w);
    float sws = swtch[e] * 0.25f;
    float4* wp = reinterpret_cast<float4*>(g_w + (ll)e * 16);
    #pragma unroll
    for (int d4 = 0; d4 < 4; d4++)
        wp[d4] = make_float4(w[4*d4] * sws, w[4*d4+1] * sws, w[4*d4+2] * sws, w[4*d4+3] * sws);
}

// ---------------- fused layer-1 ur gather + MLP (parallel phase A) ----------------
#define U2PAD 264
__global__ __launch_bounds__(256) void ur1mlp1_kernel(
    const int* __restrict__ src, const int* __restrict__ dst,
    const float* __restrict__ dist, const float* __restrict__ swtch,
    const float* __restrict__ pw1, const float* __restrict__ pb1,
    const float* __restrict__ pw2, const float* __restrict__ pb2)
{
    __shared__ float4 s_pw1[256];   // 32x32
    __shared__ float4 s_pw2[128];   // 32x16
    __shared__ float  s_b1[32];
    __shared__ float  s_b2[16];
    __shared__ float  s_u2[16][U2PAD];

    int tid = threadIdx.x;
    for (int i = tid; i < 256; i += 256) s_pw1[i] = reinterpret_cast<const float4*>(pw1)[i];
    for (int i = tid; i < 128; i += 256) s_pw2[i] = reinterpret_cast<const float4*>(pw2)[i];
    if (tid < 32) s_b1[tid] = pb1[tid];
    if (tid < 16) s_b2[tid] = pb2[tid];
    __syncthreads();

    int wid = tid >> 5, lane = tid & 31;
    int base = blockIdx.x * 256;
    int tap = lane & 3;
    int eo  = lane >> 2;   // 0..7

    #pragma unroll
    for (int it = 0; it < 4; it++) {
        int e_loc = wid * 32 + it * 8 + eo;
        int e = base + e_loc;
        if (e < EE) {
            int is = src[e], id = dst[e];
            const float4* Yp = reinterpret_cast<const float4*>(g_Y + e * 16);
            float Yv[16];
            #pragma unroll
            for (int q = 0; q < 4; q++) {
                float4 y4 = Yp[q];
                Yv[4*q]=y4.x; Yv[4*q+1]=y4.y; Yv[4*q+2]=y4.z; Yv[4*q+3]=y4.w;
            }
            const float4* Vd4 = reinterpret_cast<const float4*>(&g_Vi[(ll)id * 64 + tap * 16]);
            const float4* Vs4 = reinterpret_cast<const float4*>(&g_Vi[(ll)is * 64 + tap * 16]);
            float Vd[16], Vs[16];
            #pragma unroll
            for (int q = 0; q < 4; q++) {
                float4 a4 = Vd4[q], b4 = Vs4[q];
                Vd[4*q]=a4.x; Vd[4*q+1]=a4.y; Vd[4*q+2]=a4.z; Vd[4*q+3]=a4.w;
                Vs[4*q]=b4.x; Vs[4*q+1]=b4.y; Vs[4*q+2]=b4.z; Vs[4*q+3]=b4.w;
            }
            float u0 = (Vd[0] + Vs[0]) * Yv[0];
            float u1 = 0.f, u2 = 0.f, u3 = 0.f;
            #pragma unroll
            for (int m = 1; m < 4; m++)  u1 += (Vd[m] - Vs[m]) * Yv[m];
            #pragma unroll
            for (int m = 4; m < 9; m++)  u2 += (Vd[m] + Vs[m]) * Yv[m];
            #pragma unroll
            for (int m = 9; m < 16; m++) u3 += (Vd[m] - Vs[m]) * Yv[m];
            s_u2[ 0 + tap][e_loc] = u0;
            s_u2[ 4 + tap][e_loc] = u1;
            s_u2[ 8 + tap][e_loc] = u2;
            s_u2[12 + tap][e_loc] = u3;
        }
    }
    __syncthreads();

    int e = base + tid;
    if (e >= EE) return;
    float u[32];
    radial_eval(dist[e], u);
    #pragma unroll
    for (int j = 0; j < 16; j++) u[16 + j] = s_u2[j][tid];
    float w[16];
    mlp_eval<32>(u, s_pw1, s_b1, s_pw2, s_b2, w);
    float sws = swtch[e] * 0.25f;
    float4* wp = reinterpret_cast<float4*>(g_w + (ll)e * 16);
    #pragma unroll
    for (int d4 = 0; d4 < 4; d4++)
        wp[d4] = make_float4(w[4*d4] * sws, w[4*d4+1] * sws, w[4*d4+2] * sws, w[4*d4+3] * sws);
}

// ---------------- QKV HGEMM via mma.sync (fp16 in, fp32 acc) ----------------
// block tile 128x128, 8 warps (2x4), warp tile 64x32 (4x4 mma of 16x8)
#define APAD 24    // halves per A row (conflict-free: 48B stride)
#define BPADH2 136 // half2 per B k-pair row (conflict-free: 544B stride)
__global__ __launch_bounds__(256, 2) void hgemm_qkv_kernel(
    const float* __restrict__ wq, const float* __restrict__ wk,
    const float* __restrict__ wv)
{
    __shared__ __half  As[2][128][APAD];    // 12 KB
    __shared__ __half2 Bs[2][8][BPADH2];    // 8.5 KB
    int tid = threadIdx.x;
    int warp = tid >> 5, lane = tid & 31;
    int warpM = warp >> 2, warpN = warp & 3;
    int row0 = blockIdx.y * 128;
    int col0 = blockIdx.x * 128;
    int qg = lane & 3;     // thread-in-group
    int rg = lane >> 2;    // group id

    float acc[4][4][4];
    #pragma unroll
    for (int mt = 0; mt < 4; mt++)
        #pragma unroll
        for (int nt = 0; nt < 4; nt++)
            #pragma unroll
            for (int i = 0; i < 4; i++) acc[mt][nt][i] = 0.f;

    const int ar  = tid >> 1;
    const int ac0 = (tid & 1) * 8;
    const int agrow = row0 + ar;
    const int bbr = tid >> 4;          // k row 0..15
    const int bbc = (tid & 15) * 8;    // n
    const int bgcol = col0 + bbc;

    float4 pa0, pa1, pb0, pb1;
    // preload kt = 0
    {
        pa0 = make_float4(0,0,0,0); pa1 = make_float4(0,0,0,0);
        if (agrow < NN) {
            const float* s = g_xi + (ll)agrow * DIM + ac0;
            pa0 = *reinterpret_cast<const float4*>(s);
            pa1 = *reinterpret_cast<const float4*>(s + 4);
        }
        pb0 = make_float4(0,0,0,0); pb1 = make_float4(0,0,0,0);
        if (bgcol < QKVW) {
            const float* srcp; int c;
            if (bgcol < 320)      { srcp = wq + (ll)bbr * 320; c = bgcol; }
            else if (bgcol < 640) { srcp = wk + (ll)bbr * 320; c = bgcol - 320; }
            else                  { srcp = wv + (ll)bbr * 176; c = bgcol - 640; }
            pb0 = *reinterpret_cast<const float4*>(srcp + c);
            pb1 = *reinterpret_cast<const float4*>(srcp + c + 4);
        }
        // store A (8 halves, one uint4)
        __half2 h0 = __floats2half2_rn(pa0.x, pa0.y);
        __half2 h1 = __floats2half2_rn(pa0.z, pa0.w);
        __half2 h2 = __floats2half2_rn(pa1.x, pa1.y);
        __half2 h3 = __floats2half2_rn(pa1.z, pa1.w);
        uint4 av;
        av.x = *reinterpret_cast<u32*>(&h0); av.y = *reinterpret_cast<u32*>(&h1);
        av.z = *reinterpret_cast<u32*>(&h2); av.w = *reinterpret_cast<u32*>(&h3);
        *reinterpret_cast<uint4*>(&As[0][ar][ac0]) = av;
        // store B (8 halves scattered into pair-packed layout)
        int p = bbr >> 1, par = bbr & 1;
        float bf[8] = {pb0.x, pb0.y, pb0.z, pb0.w, pb1.x, pb1.y, pb1.z, pb1.w};
        #pragma unroll
        for (int i = 0; i < 8; i++)
            reinterpret_cast<__half*>(&Bs[0][p][bbc + i])[par] = __float2half(bf[i]);
    }
    __syncthreads();

    for (int kt = 0; kt < 11; ++kt) {
        int cur = kt & 1, nxt = cur ^ 1;
        bool has_nxt = (kt + 1 < 11);
        if (has_nxt) {
            int gkbase = (kt + 1) * 16;
            pa0 = make_float4(0,0,0,0); pa1 = make_float4(0,0,0,0);
            if (agrow < NN) {
                const float* s = g_xi + (ll)agrow * DIM + gkbase + ac0;
                pa0 = *reinterpret_cast<const float4*>(s);
                pa1 = *reinterpret_cast<const float4*>(s + 4);
            }
            int gk = gkbase + bbr;
            pb0 = make_float4(0,0,0,0); pb1 = make_float4(0,0,0,0);
            if (bgcol < QKVW) {
                const float* srcp; int c;
                if (bgcol < 320)      { srcp = wq + (ll)gk * 320; c = bgcol; }
                else if (bgcol < 640) { srcp = wk + (ll)gk * 320; c = bgcol - 320; }
                else                  { srcp = wv + (ll)gk * 176; c = bgcol - 640; }
                pb0 = *reinterpret_cast<const float4*>(srcp + c);
                pb1 = *reinterpret_cast<const float4*>(srcp + c + 4);
            }
        }
        // fragments + mma
        u32 bfr[4][2];
        #pragma unroll
        for (int nt = 0; nt < 4; nt++) {
            int cB = warpN * 32 + nt * 8 + rg;
            bfr[nt][0] = *reinterpret_cast<const u32*>(&Bs[cur][qg][cB]);
            bfr[nt][1] = *reinterpret_cast<const u32*>(&Bs[cur][qg + 4][cB]);
        }
        #pragma unroll
        for (int mt = 0; mt < 4; mt++) {
            const __half* Ab = &As[cur][warpM * 64 + mt * 16 + rg][qg * 2];
            u32 a[4];
            a[0] = *reinterpret_cast<const u32*>(Ab);
            a[1] = *reinterpret_cast<const u32*>(Ab + 8 * APAD);
            a[2] = *reinterpret_cast<const u32*>(Ab + 8);
            a[3] = *reinterpret_cast<const u32*>(Ab + 8 * APAD + 8);
            #pragma unroll
            for (int nt = 0; nt < 4; nt++)
                mma16816(acc[mt][nt], a, bfr[nt], acc[mt][nt]);
        }
        if (has_nxt) {
            __half2 h0 = __floats2half2_rn(pa0.x, pa0.y);
            __half2 h1 = __floats2half2_rn(pa0.z, pa0.w);
            __half2 h2 = __floats2half2_rn(pa1.x, pa1.y);
            __half2 h3 = __floats2half2_rn(pa1.z, pa1.w);
            uint4 av;
            av.x = *reinterpret_cast<u32*>(&h0); av.y = *reinterpret_cast<u32*>(&h1);
            av.z = *reinterpret_cast<u32*>(&h2); av.w = *reinterpret_cast<u32*>(&h3);
            *reinterpret_cast<uint4*>(&As[nxt][ar][ac0]) = av;
            int p = bbr >> 1, par = bbr & 1;
            float bf[8] = {pb0.x, pb0.y, pb0.z, pb0.w, pb1.x, pb1.y, pb1.z, pb1.w};
            #pragma unroll
            for (int i = 0; i < 8; i++)
                reinterpret_cast<__half*>(&Bs[nxt][p][bbc + i])[par] = __float2half(bf[i]);
            __syncthreads();
        }
    }

    // epilogue: c0,c1 at (row, gc..gc+1); c2,c3 at (row+8, gc..gc+1)
    #pragma unroll
    for (int mt = 0; mt < 4; mt++) {
        int row = row0 + warpM * 64 + mt * 16 + rg;
        #pragma unroll
        for (int nt = 0; nt < 4; nt++) {
            int gc = col0 + warpN * 32 + nt * 8 + qg * 2;
            if (gc >= QKVW) continue;
            #pragma unroll
            for (int half_m = 0; half_m < 2; half_m++) {
                int gr = row + half_m * 8;
                if (gr >= NN) continue;
                float fx = acc[mt][nt][half_m * 2];
                float fy = acc[mt][nt][half_m * 2 + 1];
                if (gc < 640) {
                    int blk = (gc < 320) ? 0 : 320;
                    int c = gc - blk;
                    int h = c >> 4, d = c & 15;
                    int oc = blk + ((d >> 2) * 20 + h) * 4 + (d & 3);  // pair-preserving (d even)
                    __half2 hv = __floats2half2_rn(fx, fy);
                    *reinterpret_cast<__half2*>(&g_qkh[(ll)gr * 640 + oc]) = hv;
                } else {
                    float2 f = make_float2(fx, fy);
                    *reinterpret_cast<float2*>(&g_v[(ll)gr * DIM + (gc - 640)]) = f;
                }
            }
        }
    }
}

// ---------------- update SGEMM (double-buffered, plain-A smem): G = [xi|mi] @ uw ----------------
__global__ __launch_bounds__(256, 2) void sgemm_upd_kernel(const float* __restrict__ B)
{
    __shared__ float As[2][16][128];
    __shared__ float Bs[2][16][128];
    int tid = threadIdx.x;
    int tx = tid & 15, ty = tid >> 4;
    int row0 = blockIdx.y * 128;
    int col0 = blockIdx.x * 128;
    u64 acc[8][4];
    #pragma unroll
    for (int i = 0; i < 8; i++)
        #pragma unroll
        for (int j = 0; j < 4; j++) acc[i][j] = 0ull;

    const int ar = tid >> 1;
    const int ac0 = (tid & 1) * 8;
    const int agrow = row0 + ar;
    const int bbr = tid >> 4;
    const int bbc = (tid & 15) * 8;
    const int bgcol = col0 + bbc;

    float4 pa0, pa1, pb0, pb1;
    {
        pa0 = make_float4(0,0,0,0); pa1 = make_float4(0,0,0,0);
        if (agrow < NN) {
            const float* s = g_xi + (ll)agrow * DIM + ac0;
            pa0 = *reinterpret_cast<const float4*>(s);
            pa1 = *reinterpret_cast<const float4*>(s + 4);
        }
        pb0 = make_float4(0,0,0,0); pb1 = make_float4(0,0,0,0);
        if (bgcol < DIM) {
            const float* s = B + (ll)bbr * DIM + bgcol;
            pb0 = *reinterpret_cast<const float4*>(s);
            pb1 = *reinterpret_cast<const float4*>(s + 4);
        }
        As[0][ac0+0][ar] = pa0.x;
        As[0][ac0+1][ar] = pa0.y;
        As[0][ac0+2][ar] = pa0.z;
        As[0][ac0+3][ar] = pa0.w;
        As[0][ac0+4][ar] = pa1.x;
        As[0][ac0+5][ar] = pa1.y;
        As[0][ac0+6][ar] = pa1.z;
        As[0][ac0+7][ar] = pa1.w;
        *reinterpret_cast<float4*>(&Bs[0][bbr][bbc])     = pb0;
        *reinterpret_cast<float4*>(&Bs[0][bbr][bbc + 4]) = pb1;
    }
    __syncthreads();

    for (int kt = 0; kt < 22; ++kt) {
        int cur = kt & 1, nxt = cur ^ 1;
        bool has_nxt = (kt + 1 < 22);
        if (has_nxt) {
            int gkbase = (kt + 1) * 16;
            const float* Ap = (gkbase < DIM) ? g_xi : g_mi;
            int koff = (gkbase < DIM) ? gkbase : gkbase - DIM;
            pa0 = make_float4(0,0,0,0); pa1 = make_float4(0,0,0,0);
            if (agrow < NN) {
                const float* s = Ap + (ll)agrow * DIM + koff + ac0;
                pa0 = *reinterpret_cast<const float4*>(s);
                pa1 = *reinterpret_cast<const float4*>(s + 4);
            }
            int gk = gkbase + bbr;
            pb0 = make_float4(0,0,0,0); pb1 = make_float4(0,0,0,0);
            if (bgcol < DIM) {
                const float* s = B + (ll)gk * DIM + bgcol;
                pb0 = *reinterpret_cast<const float4*>(s);
                pb1 = *reinterpret_cast<const float4*>(s + 4);
            }
        }
        #pragma unroll
        for (int k = 0; k < 16; ++k) {
            const float4* ap = reinterpret_cast<const float4*>(&As[cur][k][ty * 8]);
            float4 af0 = ap[0], af1 = ap[1];
            u64 a[8];
            a[0] = pack2(af0.x, af0.x); a[1] = pack2(af0.y, af0.y);
            a[2] = pack2(af0.z, af0.z); a[3] = pack2(af0.w, af0.w);
            a[4] = pack2(af1.x, af1.x); a[5] = pack2(af1.y, af1.y);
            a[6] = pack2(af1.z, af1.z); a[7] = pack2(af1.w, af1.w);
            u64 b[4];
            {
                const ulonglong2* p = reinterpret_cast<const ulonglong2*>(&Bs[cur][k][tx * 8]);
                ulonglong2 w0 = p[0], w1 = p[1];
                b[0]=w0.x; b[1]=w0.y; b[2]=w1.x; b[3]=w1.y;
            }
            #pragma unroll
            for (int i = 0; i < 8; i++)
                #pragma unroll
                for (int j = 0; j < 4; j++)
                    fma2(acc[i][j], a[i], b[j]);
        }
        if (has_nxt) {
            As[nxt][ac0+0][ar] = pa0.x;
            As[nxt][ac0+1][ar] = pa0.y;
            As[nxt][ac0+2][ar] = pa0.z;
            As[nxt][ac0+3][ar] = pa0.w;
            As[nxt][ac0+4][ar] = pa1.x;
            As[nxt][ac0+5][ar] = pa1.y;
            As[nxt][ac0+6][ar] = pa1.z;
            As[nxt][ac0+7][ar] = pa1.w;
            *reinterpret_cast<float4*>(&Bs[nxt][bbr][bbc])     = pb0;
            *reinterpret_cast<float4*>(&Bs[nxt][bbr][bbc + 4]) = pb1;
            __syncthreads();
        }
    }
    #pragma unroll
    for (int i = 0; i < 8; i++) {
        int gr = row0 + ty * 8 + i;
        if (gr >= NN) continue;
        #pragma unroll
        for (int j = 0; j < 4; j++) {
            int gc = col0 + tx * 8 + j * 2;
            if (gc < DIM) {
                float2 f = unpack2(acc[i][j]);
                *reinterpret_cast<float2*>(&g_G[(ll)gr * DIM + gc]) = f;
            }
        }
    }
}

// ---------------- slim edge attention + scatter (fp16 q/k, HMUL2 products) ----------------
template<int LAYER>
__global__ __launch_bounds__(256) void edge_attn_kernel(
    const int* __restrict__ src, const int* __restrict__ dst)
{
    __shared__ float s_a[8][20];

    int tid = threadIdx.x;
    int wid = tid >> 5, lane = tid & 31;
    int b0a = 4 * lane;
    int b0b = 4 * (lane + 32);
    int hA0 =  b0a      / VD, hA1 = (b0a + 1) / VD, hA2 = (b0a + 2) / VD, hA3 = (b0a + 3) / VD;
    int hB0 =  b0b      / VD, hB1 = (b0b + 1) / VD, hB2 = (b0b + 2) / VD, hB3 = (b0b + 3) / VD;

    for (int e = blockIdx.x * 8 + wid; e < EE; e += gridDim.x * 8) {
        int is = src[e], id = dst[e];
        float4 y4;
        if (LAYER == 0 && lane < 16)
            y4 = __ldg(reinterpret_cast<const float4*>(g_Y) + e * 4 + (lane & 3));
        const uint2* qh = reinterpret_cast<const uint2*>(g_qkh + (ll)id * 640);
        const uint2* kh = reinterpret_cast<const uint2*>(g_qkh + (ll)is * 640 + 320);
        const float4* wp = reinterpret_cast<const float4*>(g_w + (ll)e * 16);
        const float* vr = g_v + (ll)is * DIM;
        float4 v4a = *reinterpret_cast<const float4*>(vr + b0a);
        float4 v4b = make_float4(0, 0, 0, 0);
        if (lane < 12) v4b = *reinterpret_cast<const float4*>(vr + b0b);
        if (lane < 20) {
            float a0 = 0.f, a1 = 0.f;
            #pragma unroll
            for (int d4 = 0; d4 < 4; d4++) {
                uint2 qu = __ldg(qh + d4 * 20 + lane);
                uint2 ku = __ldg(kh + d4 * 20 + lane);
                float4 w4 = __ldg(wp + d4);
                __half2 p0 = __hmul2(*reinterpret_cast<__half2*>(&qu.x),
                                     *reinterpret_cast<__half2*>(&ku.x));
                __half2 p1 = __hmul2(*reinterpret_cast<__half2*>(&qu.y),
                                     *reinterpret_cast<__half2*>(&ku.y));
                float2 f0 = __half22float2(p0);
                float2 f1 = __half22float2(p1);
                a0 += f0.x * w4.x + f0.y * w4.y;
                a1 += f1.x * w4.z + f1.y * w4.w;
            }
            s_a[wid][lane] = a0 + a1;
        }
        __syncwarp();
        float* mr = &g_mi[(ll)id * DIM];
        {
            float4 o;
            o.x = s_a[wid][hA0] * v4a.x;
            o.y = s_a[wid][hA1] * v4a.y;
            o.z = s_a[wid][hA2] * v4a.z;
            o.w = s_a[wid][hA3] * v4a.w;
            atomicAdd(reinterpret_cast<float4*>(mr + b0a), o);
        }
        if (lane < 12) {
            float4 o;
            o.x = s_a[wid][hB0] * v4b.x;
            o.y = s_a[wid][hB1] * v4b.y;
            o.z = s_a[wid][hB2] * v4b.z;
            o.w = s_a[wid][hB3] * v4b.w;
            atomicAdd(reinterpret_cast<float4*>(mr + b0b), o);
        }
        if (LAYER == 0) {
            if (lane < 16) {
                float at = s_a[wid][16 + (lane >> 2)];
                float4 o = make_float4(at * y4.x, at * y4.y, at * y4.z, at * y4.w);
                atomicAdd(reinterpret_cast<float4*>(&g_Vi[(ll)id * 64 + 4 * lane]), o);
            }
        }
        __syncwarp();
    }
}

// ---------------- residual + LayerNorm (+ zero mi for next layer) ----------------
__global__ void resln_kernel(const float* __restrict__ ub, float* __restrict__ out, int toXi) {
    __shared__ float red[8];
    int n = blockIdx.x, t = threadIdx.x;
    float val = 0.f;
    if (t < DIM) val = g_xi[n * DIM + t] + g_G[n * DIM + t] + ub[t];
    float mu = block_sum_192(val, red) * (1.f / DIM);
    float dx = (t < DIM) ? (val - mu) : 0.f;
    float var = block_sum_192(dx * dx, red) * (1.f / DIM);
    if (t < DIM) {
        float o = dx * rsqrtf(var + 1e-6f);
        if (toXi) {
            g_xi[n * DIM + t] = o;
            g_mi[(ll)n * DIM + t] = 0.f;
        } else {
            out[n * DIM + t] = o;
        }
    }
}

// ---------------- launch ----------------
extern "C" void kernel_launch(void* const* d_in, const int* in_sizes, int n_in,
                              void* d_out, int out_size) {
    const int*   species  = (const int*)  d_in[0];
    const float* dist     = (const float*)d_in[1];
    const float* swtch    = (const float*)d_in[2];
    const int*   esrc     = (const int*)  d_in[3];
    const int*   edst     = (const int*)  d_in[4];
    const float* vec      = (const float*)d_in[5];
    const float* z_table  = (const float*)d_in[6];
    const float* w_sp     = (const float*)d_in[7];
    const float* pw1_0    = (const float*)d_in[8];
    const float* pb1_0    = (const float*)d_in[9];
    const float* pw2_0    = (const float*)d_in[10];
    const float* pb2_0    = (const float*)d_in[11];
    const float* wq_0     = (const float*)d_in[12];
    const float* wk_0     = (const float*)d_in[13];
    const float* wv_0     = (const float*)d_in[14];
    const float* uw_0     = (const float*)d_in[15];
    const float* ub_0     = (const float*)d_in[16];
    const float* pw1_1    = (const float*)d_in[17];
    const float* pb1_1    = (const float*)d_in[18];
    const float* pw2_1    = (const float*)d_in[19];
    const float* pb2_1    = (const float*)d_in[20];
    const float* wq_1     = (const float*)d_in[21];
    const float* wk_1     = (const float*)d_in[22];
    const float* wv_1     = (const float*)d_in[23];
    const float* uw_1     = (const float*)d_in[24];
    const float* ub_1     = (const float*)d_in[25];
    float* out = (float*)d_out;

    const int EB  = (EE + 255) / 256;
    const int EWB = 740;
    dim3 grid_qkv(7, 79);
    dim3 grid_upd(2, 79);

    node_embed_kernel<<<NN, 192>>>(species, z_table, w_sp);                            // 0
    edge_geom_kernel<<<EB, 256>>>(dist, vec, swtch, pw1_0, pb1_0, pw2_0, pb2_0);       // 1

    // ---- layer 0 ----
    hgemm_qkv_kernel<<<grid_qkv, 256>>>(wq_0, wk_0, wv_0);                             // 2
    edge_attn_kernel<0><<<EWB, 256>>>(esrc, edst);                                     // 3 (profiled)
    sgemm_upd_kernel<<<grid_upd, 256>>>(uw_0);                                         // 4
    resln_kernel<<<NN, 192>>>(ub_0, out, 1);                                           // 5

    // ---- layer 1 ----
    ur1mlp1_kernel<<<EB, 256>>>(esrc, edst, dist, swtch, pw1_1, pb1_1, pw2_1, pb2_1);  // 6
    hgemm_qkv_kernel<<<grid_qkv, 256>>>(wq_1, wk_1, wv_1);                             // 7
    edge_attn_kernel<1><<<EWB, 256>>>(esrc, edst);                                     // 8
    sgemm_upd_kernel<<<grid_upd, 256>>>(uw_1);                                         // 9
    resln_kernel<<<NN, 192>>>(ub_1, out, 0);                                           // 10
}